// round 10
// baseline (speedup 1.0000x reference)
#include <cuda_runtime.h>

#define NEG 0.2f

// Scratch (__device__ globals; no allocation allowed)
__device__ float          gH[8 * 1024 * 128];     // projected features (4 MB)
__device__ float2         gE[32 * 1024];          // (e1,e2) sorted order
__device__ unsigned short gPerm[32 * 1024];
__device__ int            gStarts[32 * 1026];     // bucket starts
__device__ float2         gQC[32 * 1024];         // per-query (c1,c2), bucket order
__device__ unsigned short gQOut[32 * 1024];       // original query idx, bucket order

struct GemmS {
    float As[16][128];
    float Bs[16][128];
};

struct ScalS {
    float          ws[128], wd[128];
    float          sS[1024];
    float          dvA[1024], dvB[1024];
    float2         pe[1024];
    float2         wsum2[32];
    unsigned short pmA[1024], pmB[1024];
    int            wsumI[32];
    int            cnt[1025];
    int            starts[1026];
};

struct VecS {
    float2         sE[1024];
    float          t1s[32][32], t2s[32][32];
    float          sHr[256 * 32];      // 8 emit segments x 32 rows (32 KB)
    float2         sQc[1024];
    unsigned short sQo[1024];
    unsigned short sPm[1024];
    int            sStarts[1026];
};

__device__ __forceinline__ void shfl_pass(float& v, int& idx, int j, int k, int tid) {
    float pv = __shfl_xor_sync(0xFFFFFFFFu, v, j);
    int   pi = __shfl_xor_sync(0xFFFFFFFFu, idx, j);
    bool  up   = ((tid & k) == 0);
    bool  iLow = ((tid & j) == 0);
    float lo = iLow ? v : pv, hi = iLow ? pv : v;
    bool  sw = up ? (lo > hi) : (lo < hi);
    if (sw) { v = pv; idx = pi; }
}

// ---------------------------------------------------------------------------
// Kernel A: blocks 0..31 scalar phase (independent of gemm), 32..95 gemm.
// ---------------------------------------------------------------------------
__global__ __launch_bounds__(1024) void fusedA(const float* __restrict__ x,
                                               const float* __restrict__ W,
                                               const float* __restrict__ a_src,
                                               const float* __restrict__ a_dst) {
    extern __shared__ float4 sraw4[];
    char* sraw = reinterpret_cast<char*>(sraw4);
    const int tid = threadIdx.x, lane = tid & 31, wid = tid >> 5;

    if (blockIdx.x >= 32) {
        // ================= GEMM block: 128x128 tile, 4x4 per thread ========
        GemmS& G = *reinterpret_cast<GemmS*>(sraw);
        const int bm = (blockIdx.x - 32) * 128;
        float acc[4][4];
#pragma unroll
        for (int i = 0; i < 4; i++)
#pragma unroll
            for (int j = 0; j < 4; j++) acc[i][j] = 0.f;

        for (int k0 = 0; k0 < 128; k0 += 16) {
#pragma unroll 2
            for (int i = tid; i < 2048; i += 1024) {
                int m = i >> 4, kk = i & 15;
                G.As[kk][m] = x[(size_t)(bm + m) * 128 + k0 + kk];
            }
#pragma unroll 2
            for (int i = tid; i < 2048; i += 1024) {
                int kk = i >> 7, n = i & 127;
                G.Bs[kk][n] = W[(size_t)(k0 + kk) * 128 + n];
            }
            __syncthreads();
#pragma unroll
            for (int kk = 0; kk < 16; kk++) {
                float4 av = reinterpret_cast<float4*>(G.As[kk])[wid];   // broadcast
                float4 bv = reinterpret_cast<float4*>(G.Bs[kk])[lane];
                float a[4]  = {av.x, av.y, av.z, av.w};
                float bb[4] = {bv.x, bv.y, bv.z, bv.w};
#pragma unroll
                for (int i = 0; i < 4; i++)
#pragma unroll
                    for (int j = 0; j < 4; j++) acc[i][j] = fmaf(a[i], bb[j], acc[i][j]);
            }
            __syncthreads();
        }
#pragma unroll
        for (int i = 0; i < 4; i++)
            *reinterpret_cast<float4*>(&gH[(size_t)(bm + wid * 4 + i) * 128 + lane * 4]) =
                make_float4(acc[i][0], acc[i][1], acc[i][2], acc[i][3]);
        return;
    }

    // ================= Scalar block: per (b, head) =========================
    ScalS& S = *reinterpret_cast<ScalS*>(sraw);
    const int bh = blockIdx.x, b = bh >> 2, head = bh & 3;

    // --- projected attention vectors: ws = W[:,head]·a_src, wd likewise ---
    {
        int k = tid >> 3, c8 = tid & 7;
        float4 wv  = *reinterpret_cast<const float4*>(W + (size_t)k * 128 + head * 32 + c8 * 4);
        float4 as4 = *reinterpret_cast<const float4*>(a_src + head * 32 + c8 * 4);
        float4 ad4 = *reinterpret_cast<const float4*>(a_dst + head * 32 + c8 * 4);
        float ps = wv.x * as4.x + wv.y * as4.y + wv.z * as4.z + wv.w * as4.w;
        float pd = wv.x * ad4.x + wv.y * ad4.y + wv.z * ad4.z + wv.w * ad4.w;
#pragma unroll
        for (int o = 4; o >= 1; o >>= 1) {
            ps += __shfl_xor_sync(0xFFFFFFFFu, ps, o);
            pd += __shfl_xor_sync(0xFFFFFFFFu, pd, o);
        }
        if (c8 == 0) { S.ws[k] = ps; S.wd[k] = pd; }
    }
    __syncthreads();

    // --- dots from x directly: warp wid handles rows wid*32..+31 ---
    {
        float4 wsv = reinterpret_cast<float4*>(S.ws)[lane];
        float4 wdv = reinterpret_cast<float4*>(S.wd)[lane];
        const float4* xb = reinterpret_cast<const float4*>(x + (size_t)b * 1024 * 128);
        for (int jj = 0; jj < 32; jj++) {
            int row = wid * 32 + jj;
            float4 xv = xb[row * 32 + lane];
            float pd = xv.x * wdv.x + xv.y * wdv.y + xv.z * wdv.z + xv.w * wdv.w;
            float ps = xv.x * wsv.x + xv.y * wsv.y + xv.z * wsv.z + xv.w * wsv.w;
#pragma unroll
            for (int o = 16; o >= 1; o >>= 1) {
                pd += __shfl_xor_sync(0xFFFFFFFFu, pd, o);
                ps += __shfl_xor_sync(0xFFFFFFFFu, ps, o);
            }
            if (lane == 0) { S.dvA[row] = pd; S.sS[row] = ps; }
        }
    }
    __syncthreads();

    float v   = S.dvA[tid];
    float s   = S.sS[tid];
    int   idx = tid;

    // --- bitonic sort: k=2..32 in registers (shfl) ---
#pragma unroll
    for (int k = 2; k <= 32; k <<= 1)
#pragma unroll
        for (int j = k >> 1; j >= 1; j >>= 1) shfl_pass(v, idx, j, k, tid);

    float*          dvc = S.dvA;  float*          dvn = S.dvB;
    unsigned short* pmc = S.pmA;  unsigned short* pmn = S.pmB;
    dvc[tid] = v; pmc[tid] = (unsigned short)idx;
    __syncthreads();

    // --- k=64..1024: ping-pong cross-warp passes + shfl tails ---
    for (int k = 64; k <= 1024; k <<= 1) {
        for (int j = k >> 1; j >= 32; j >>= 1) {
            float          v0 = dvc[tid];
            unsigned short i0 = pmc[tid];
            float          pv = dvc[tid ^ j];
            unsigned short pi = pmc[tid ^ j];
            bool  up   = ((tid & k) == 0);
            bool  iLow = ((tid & j) == 0);
            float lo = iLow ? v0 : pv, hi = iLow ? pv : v0;
            bool  sw = up ? (lo > hi) : (lo < hi);
            dvn[tid] = sw ? pv : v0;
            pmn[tid] = sw ? pi : i0;
            __syncthreads();
            float* tf = dvc; dvc = dvn; dvn = tf;
            unsigned short* tp = pmc; pmc = pmn; pmn = tp;
        }
        v = dvc[tid]; idx = pmc[tid];
#pragma unroll
        for (int j = 16; j >= 1; j >>= 1) shfl_pass(v, idx, j, k, tid);
        dvc[tid] = v; pmc[tid] = (unsigned short)idx;
        __syncthreads();
    }
    const float*          dvf = dvc;
    const unsigned short* pmf = pmc;

    // --- exps ---
    const float dmax = dvf[1023];
    float  xx = v - dmax;
    float2 ev = make_float2(__expf(xx), __expf(NEG * xx));
    gE[bh * 1024 + tid]    = ev;
    gPerm[bh * 1024 + tid] = pmf[tid];

    // --- fused inclusive block scan of (e1, e2) ---
    {
        float2 sv = ev;
#pragma unroll
        for (int off = 1; off < 32; off <<= 1) {
            float nx = __shfl_up_sync(0xFFFFFFFFu, sv.x, off);
            float ny = __shfl_up_sync(0xFFFFFFFFu, sv.y, off);
            if (lane >= off) { sv.x += nx; sv.y += ny; }
        }
        if (lane == 31) S.wsum2[wid] = sv;
        __syncthreads();
        if (wid == 0) {
            float2 w = S.wsum2[lane];
#pragma unroll
            for (int off = 1; off < 32; off <<= 1) {
                float nx = __shfl_up_sync(0xFFFFFFFFu, w.x, off);
                float ny = __shfl_up_sync(0xFFFFFFFFu, w.y, off);
                if (lane >= off) { w.x += nx; w.y += ny; }
            }
            S.wsum2[lane] = w;
        }
        __syncthreads();
        if (wid) { float2 c = S.wsum2[wid - 1]; sv.x += c.x; sv.y += c.y; }
        S.pe[tid] = sv;
        __syncthreads();
    }

    // --- binary search + per-query coefficients ---
    float c1c, c2c;
    int   kk;
    {
        const float T1 = S.pe[1023].x;
        float key = -s;
        int   k   = 0;
#pragma unroll
        for (int step = 1024; step >= 1; step >>= 1) {
            int nk = k + step;
            if (nk <= 1024 && dvf[nk - 1] < key) k = nk;
        }
        kk = k;
        float u  = s + dmax;
        float m  = fmaxf(u, NEG * u);
        float w1 = __expf(u - m);
        float w2 = __expf(NEG * u - m);
        float2 P = (k > 0) ? S.pe[k - 1] : make_float2(0.f, 0.f);
        float den = fmaf(w1, T1 - P.x, w2 * P.y);
        float inv = 1.f / den;
        c1c = w1 * inv;
        c2c = w2 * inv;
    }

    // --- counting sort of queries by bucket = k ---
    for (int i = tid; i < 1025; i += 1024) S.cnt[i] = 0;
    __syncthreads();
    atomicAdd(&S.cnt[kk], 1);
    __syncthreads();
    {
        int cv = S.cnt[tid];
#pragma unroll
        for (int off = 1; off < 32; off <<= 1) {
            int n = __shfl_up_sync(0xFFFFFFFFu, cv, off);
            if (lane >= off) cv += n;
        }
        if (lane == 31) S.wsumI[wid] = cv;
        __syncthreads();
        if (wid == 0) {
            int w = S.wsumI[lane];
#pragma unroll
            for (int off = 1; off < 32; off <<= 1) {
                int n = __shfl_up_sync(0xFFFFFFFFu, w, off);
                if (lane >= off) w += n;
            }
            S.wsumI[lane] = w;
        }
        __syncthreads();
        S.starts[tid + 1] = cv + (wid ? S.wsumI[wid - 1] : 0);
        if (tid == 0) S.starts[0] = 0;
        __syncthreads();
        if (tid == 0) S.starts[1025] = S.starts[1024] + S.cnt[1024];
        __syncthreads();
    }
    for (int i = tid; i < 1025; i += 1024) S.cnt[i] = 0;
    __syncthreads();
    {
        int pos = S.starts[kk] + atomicAdd(&S.cnt[kk], 1);
        gQC[bh * 1024 + pos]   = make_float2(c1c, c2c);
        gQOut[bh * 1024 + pos] = (unsigned short)tid;
    }
    for (int i = tid; i < 1026; i += 1024) gStarts[bh * 1026 + i] = S.starts[i];
}

// ---------------------------------------------------------------------------
// Kernel B: vector phase, WIDE. Grid (32 bh, 4) x 256 threads = 128 blocks.
// Each block redundantly computes ALL 32 segment totals (offsets local, no
// cross-block comm); warp w emits segment y*8+w, rows cached in smem (g==y).
// Summation order identical to the narrow version -> bit-identical outputs.
// ---------------------------------------------------------------------------
__global__ __launch_bounds__(256) void vecB2(float* __restrict__ out) {
    extern __shared__ float4 sraw4[];
    VecS& S = *reinterpret_cast<VecS*>(reinterpret_cast<char*>(sraw4));
    const int bh = blockIdx.x, y = blockIdx.y;
    const int b = bh >> 2, head = bh & 3;
    const int tid = threadIdx.x, lane = tid & 31, wid = tid >> 5;

    for (int i = tid; i < 1024; i += 256) {
        S.sE[i]  = gE[bh * 1024 + i];
        S.sPm[i] = gPerm[bh * 1024 + i];
    }
    for (int i = tid; i < 1026; i += 256) S.sStarts[i] = gStarts[bh * 1026 + i];
    __syncthreads();

    // stage this block's query slice (buckets [y*256, (y+1)*256), +1024 for y=3)
    const int q0   = S.sStarts[y * 256];
    const int qEnd = (y == 3) ? 1024 : S.sStarts[(y + 1) * 256];
    for (int t = tid; t < qEnd - q0; t += 256) {
        S.sQc[t] = gQC[bh * 1024 + q0 + t];
        S.sQo[t] = gQOut[bh * 1024 + q0 + t];
    }

    // totals for ALL 32 segments: warp wid does segments {g*8+wid : g=0..3};
    // the g==y one is this warp's emit segment — cache its rows in smem.
    const float* hhead   = gH + (size_t)b * 1024 * 128 + head * 32;
    const int    emitSeg = y * 8 + wid;
#pragma unroll
    for (int g = 0; g < 4; g++) {
        const int sg = g * 8 + wid, j0 = sg * 32;
        float t1 = 0.f, t2 = 0.f;
        const bool isEmit = (g == y);
#pragma unroll 8
        for (int jj = 0; jj < 32; jj++) {
            float  hv = hhead[(size_t)S.sPm[j0 + jj] * 128 + lane];
            if (isEmit) S.sHr[(wid * 32 + jj) * 32 + lane] = hv;
            float2 ee = S.sE[j0 + jj];
            t1 = fmaf(ee.x, hv, t1);
            t2 = fmaf(ee.y, hv, t2);
        }
        S.t1s[sg][lane] = t1;
        S.t2s[sg][lane] = t2;
    }
    __syncthreads();

    // offsets + grand total (same order as narrow version)
    float tv1 = 0.f, off1 = 0.f, off2 = 0.f;
#pragma unroll
    for (int t = 0; t < 32; t++) {
        float a  = S.t1s[t][lane];
        float b2 = S.t2s[t][lane];
        tv1 += a;
        if (t < emitSeg) { off1 += a; off2 += b2; }
    }

    // merge-emit for this warp's segment
    float acc1 = off1, acc2 = off2;
    const int l0 = emitSeg * 32;
    int    qp = S.sStarts[l0];
    float* ob = out + (size_t)(b * 1024) * 128 + head * 32 + lane;

    for (int jj = 0; jj < 32; jj++) {
        int qe = S.sStarts[l0 + jj + 1];
        while (qp < qe) {
            float2 cc = S.sQc[qp - q0];
            int    i  = S.sQo[qp - q0];
            ob[(size_t)i * 128] = fmaf(cc.x, tv1 - acc1, cc.y * acc2);
            qp++;
        }
        float  hv = S.sHr[(wid * 32 + jj) * 32 + lane];
        float2 ee = S.sE[l0 + jj];
        acc1 = fmaf(ee.x, hv, acc1);
        acc2 = fmaf(ee.y, hv, acc2);
    }
    if (emitSeg == 31) {                  // bucket k == 1024
        while (qp < 1024) {
            float2 cc = S.sQc[qp - q0];
            int    i  = S.sQo[qp - q0];
            ob[(size_t)i * 128] = fmaf(cc.x, tv1 - acc1, cc.y * acc2);
            qp++;
        }
    }
}

// ---------------------------------------------------------------------------
extern "C" void kernel_launch(void* const* d_in, const int* in_sizes, int n_in,
                              void* d_out, int out_size) {
    const float* x     = (const float*)d_in[0];
    const float* W     = (const float*)d_in[1];
    const float* a_src = (const float*)d_in[2];
    const float* a_dst = (const float*)d_in[3];
    float*       out   = (float*)d_out;

    const int smemA = (int)(sizeof(ScalS) > sizeof(GemmS) ? sizeof(ScalS) : sizeof(GemmS));
    static int smem_set = 0;
    if (!smem_set) {
        cudaFuncSetAttribute(fusedA, cudaFuncAttributeMaxDynamicSharedMemorySize, smemA);
        cudaFuncSetAttribute(vecB2, cudaFuncAttributeMaxDynamicSharedMemorySize,
                             (int)sizeof(VecS));
        smem_set = 1;
    }

    fusedA<<<96, 1024, smemA>>>(x, W, a_src, a_dst);
    vecB2<<<dim3(32, 4), 256, sizeof(VecS)>>>(out);
}

// round 12
// speedup vs baseline: 1.6860x; 1.6860x over previous
#include <cuda_runtime.h>

#define NEG 0.2f

// Scratch (__device__ globals; no allocation allowed)
__device__ float          gH[8 * 1024 * 128];     // projected features (4 MB)
__device__ float2         gE[32 * 1024];          // (e1,e2) sorted order
__device__ unsigned short gPerm[32 * 1024];
__device__ int            gStarts[32 * 1026];     // bucket starts
__device__ float2         gQC[32 * 1024];         // per-query (c1,c2), bucket order
__device__ unsigned short gQOut[32 * 1024];       // original query idx, bucket order
__device__ float2         gTot[32 * 32 * 32];     // per-(bh,seg,lane) totals (t1,t2)

struct GemmS {
    float As[16][128];
    float Bs[16][128];
};

struct ScalS {
    float          ws[128], wd[128];
    float          sS[1024];
    float          dvA[1024], dvB[1024];
    float2         pe[1024];
    float2         wsum2[32];
    unsigned short pmA[1024], pmB[1024];
    int            wsumI[32];
    int            cnt[1025];
    int            starts[1026];
};

__device__ __forceinline__ void shfl_pass(float& v, int& idx, int j, int k, int tid) {
    float pv = __shfl_xor_sync(0xFFFFFFFFu, v, j);
    int   pi = __shfl_xor_sync(0xFFFFFFFFu, idx, j);
    bool  up   = ((tid & k) == 0);
    bool  iLow = ((tid & j) == 0);
    float lo = iLow ? v : pv, hi = iLow ? pv : v;
    bool  sw = up ? (lo > hi) : (lo < hi);
    if (sw) { v = pv; idx = pi; }
}

// ---------------------------------------------------------------------------
// Kernel A: blocks 0..31 scalar phase (independent of gemm), 32..95 gemm.
// ---------------------------------------------------------------------------
__global__ __launch_bounds__(1024) void fusedA(const float* __restrict__ x,
                                               const float* __restrict__ W,
                                               const float* __restrict__ a_src,
                                               const float* __restrict__ a_dst) {
    extern __shared__ float4 sraw4[];
    char* sraw = reinterpret_cast<char*>(sraw4);
    const int tid = threadIdx.x, lane = tid & 31, wid = tid >> 5;

    if (blockIdx.x >= 32) {
        // ================= GEMM block: 128x128 tile, 4x4 per thread ========
        GemmS& G = *reinterpret_cast<GemmS*>(sraw);
        const int bm = (blockIdx.x - 32) * 128;
        float acc[4][4];
#pragma unroll
        for (int i = 0; i < 4; i++)
#pragma unroll
            for (int j = 0; j < 4; j++) acc[i][j] = 0.f;

        for (int k0 = 0; k0 < 128; k0 += 16) {
#pragma unroll 2
            for (int i = tid; i < 2048; i += 1024) {
                int m = i >> 4, kk = i & 15;
                G.As[kk][m] = x[(size_t)(bm + m) * 128 + k0 + kk];
            }
#pragma unroll 2
            for (int i = tid; i < 2048; i += 1024) {
                int kk = i >> 7, n = i & 127;
                G.Bs[kk][n] = W[(size_t)(k0 + kk) * 128 + n];
            }
            __syncthreads();
#pragma unroll
            for (int kk = 0; kk < 16; kk++) {
                float4 av = reinterpret_cast<float4*>(G.As[kk])[wid];   // broadcast
                float4 bv = reinterpret_cast<float4*>(G.Bs[kk])[lane];
                float a[4]  = {av.x, av.y, av.z, av.w};
                float bb[4] = {bv.x, bv.y, bv.z, bv.w};
#pragma unroll
                for (int i = 0; i < 4; i++)
#pragma unroll
                    for (int j = 0; j < 4; j++) acc[i][j] = fmaf(a[i], bb[j], acc[i][j]);
            }
            __syncthreads();
        }
#pragma unroll
        for (int i = 0; i < 4; i++)
            *reinterpret_cast<float4*>(&gH[(size_t)(bm + wid * 4 + i) * 128 + lane * 4]) =
                make_float4(acc[i][0], acc[i][1], acc[i][2], acc[i][3]);
        return;
    }

    // ================= Scalar block: per (b, head) =========================
    ScalS& S = *reinterpret_cast<ScalS*>(sraw);
    const int bh = blockIdx.x, b = bh >> 2, head = bh & 3;

    // --- projected attention vectors: ws = W[:,head]·a_src, wd likewise ---
    {
        int k = tid >> 3, c8 = tid & 7;
        float4 wv  = *reinterpret_cast<const float4*>(W + (size_t)k * 128 + head * 32 + c8 * 4);
        float4 as4 = *reinterpret_cast<const float4*>(a_src + head * 32 + c8 * 4);
        float4 ad4 = *reinterpret_cast<const float4*>(a_dst + head * 32 + c8 * 4);
        float ps = wv.x * as4.x + wv.y * as4.y + wv.z * as4.z + wv.w * as4.w;
        float pd = wv.x * ad4.x + wv.y * ad4.y + wv.z * ad4.z + wv.w * ad4.w;
#pragma unroll
        for (int o = 4; o >= 1; o >>= 1) {
            ps += __shfl_xor_sync(0xFFFFFFFFu, ps, o);
            pd += __shfl_xor_sync(0xFFFFFFFFu, pd, o);
        }
        if (c8 == 0) { S.ws[k] = ps; S.wd[k] = pd; }
    }
    __syncthreads();

    // --- dots from x directly: warp wid handles rows wid*32..+31 ---
    {
        float4 wsv = reinterpret_cast<float4*>(S.ws)[lane];
        float4 wdv = reinterpret_cast<float4*>(S.wd)[lane];
        const float4* xb = reinterpret_cast<const float4*>(x + (size_t)b * 1024 * 128);
        for (int jj = 0; jj < 32; jj++) {
            int row = wid * 32 + jj;
            float4 xv = xb[row * 32 + lane];
            float pd = xv.x * wdv.x + xv.y * wdv.y + xv.z * wdv.z + xv.w * wdv.w;
            float ps = xv.x * wsv.x + xv.y * wsv.y + xv.z * wsv.z + xv.w * wsv.w;
#pragma unroll
            for (int o = 16; o >= 1; o >>= 1) {
                pd += __shfl_xor_sync(0xFFFFFFFFu, pd, o);
                ps += __shfl_xor_sync(0xFFFFFFFFu, ps, o);
            }
            if (lane == 0) { S.dvA[row] = pd; S.sS[row] = ps; }
        }
    }
    __syncthreads();

    float v   = S.dvA[tid];
    float s   = S.sS[tid];
    int   idx = tid;

    // --- bitonic sort: k=2..32 in registers (shfl) ---
#pragma unroll
    for (int k = 2; k <= 32; k <<= 1)
#pragma unroll
        for (int j = k >> 1; j >= 1; j >>= 1) shfl_pass(v, idx, j, k, tid);

    float*          dvc = S.dvA;  float*          dvn = S.dvB;
    unsigned short* pmc = S.pmA;  unsigned short* pmn = S.pmB;
    dvc[tid] = v; pmc[tid] = (unsigned short)idx;
    __syncthreads();

    // --- k=64..1024: ping-pong cross-warp passes + shfl tails ---
    for (int k = 64; k <= 1024; k <<= 1) {
        for (int j = k >> 1; j >= 32; j >>= 1) {
            float          v0 = dvc[tid];
            unsigned short i0 = pmc[tid];
            float          pv = dvc[tid ^ j];
            unsigned short pi = pmc[tid ^ j];
            bool  up   = ((tid & k) == 0);
            bool  iLow = ((tid & j) == 0);
            float lo = iLow ? v0 : pv, hi = iLow ? pv : v0;
            bool  sw = up ? (lo > hi) : (lo < hi);
            dvn[tid] = sw ? pv : v0;
            pmn[tid] = sw ? pi : i0;
            __syncthreads();
            float* tf = dvc; dvc = dvn; dvn = tf;
            unsigned short* tp = pmc; pmc = pmn; pmn = tp;
        }
        v = dvc[tid]; idx = pmc[tid];
#pragma unroll
        for (int j = 16; j >= 1; j >>= 1) shfl_pass(v, idx, j, k, tid);
        dvc[tid] = v; pmc[tid] = (unsigned short)idx;
        __syncthreads();
    }
    const float*          dvf = dvc;
    const unsigned short* pmf = pmc;

    // --- exps ---
    const float dmax = dvf[1023];
    float  xx = v - dmax;
    float2 ev = make_float2(__expf(xx), __expf(NEG * xx));
    gE[bh * 1024 + tid]    = ev;
    gPerm[bh * 1024 + tid] = pmf[tid];

    // --- fused inclusive block scan of (e1, e2) ---
    {
        float2 sv = ev;
#pragma unroll
        for (int off = 1; off < 32; off <<= 1) {
            float nx = __shfl_up_sync(0xFFFFFFFFu, sv.x, off);
            float ny = __shfl_up_sync(0xFFFFFFFFu, sv.y, off);
            if (lane >= off) { sv.x += nx; sv.y += ny; }
        }
        if (lane == 31) S.wsum2[wid] = sv;
        __syncthreads();
        if (wid == 0) {
            float2 w = S.wsum2[lane];
#pragma unroll
            for (int off = 1; off < 32; off <<= 1) {
                float nx = __shfl_up_sync(0xFFFFFFFFu, w.x, off);
                float ny = __shfl_up_sync(0xFFFFFFFFu, w.y, off);
                if (lane >= off) { w.x += nx; w.y += ny; }
            }
            S.wsum2[lane] = w;
        }
        __syncthreads();
        if (wid) { float2 c = S.wsum2[wid - 1]; sv.x += c.x; sv.y += c.y; }
        S.pe[tid] = sv;
        __syncthreads();
    }

    // --- binary search + per-query coefficients ---
    float c1c, c2c;
    int   kk;
    {
        const float T1 = S.pe[1023].x;
        float key = -s;
        int   k   = 0;
#pragma unroll
        for (int step = 1024; step >= 1; step >>= 1) {
            int nk = k + step;
            if (nk <= 1024 && dvf[nk - 1] < key) k = nk;
        }
        kk = k;
        float u  = s + dmax;
        float m  = fmaxf(u, NEG * u);
        float w1 = __expf(u - m);
        float w2 = __expf(NEG * u - m);
        float2 P = (k > 0) ? S.pe[k - 1] : make_float2(0.f, 0.f);
        float den = fmaf(w1, T1 - P.x, w2 * P.y);
        float inv = 1.f / den;
        c1c = w1 * inv;
        c2c = w2 * inv;
    }

    // --- counting sort of queries by bucket = k ---
    for (int i = tid; i < 1025; i += 1024) S.cnt[i] = 0;
    __syncthreads();
    atomicAdd(&S.cnt[kk], 1);
    __syncthreads();
    {
        int cv = S.cnt[tid];
#pragma unroll
        for (int off = 1; off < 32; off <<= 1) {
            int n = __shfl_up_sync(0xFFFFFFFFu, cv, off);
            if (lane >= off) cv += n;
        }
        if (lane == 31) S.wsumI[wid] = cv;
        __syncthreads();
        if (wid == 0) {
            int w = S.wsumI[lane];
#pragma unroll
            for (int off = 1; off < 32; off <<= 1) {
                int n = __shfl_up_sync(0xFFFFFFFFu, w, off);
                if (lane >= off) w += n;
            }
            S.wsumI[lane] = w;
        }
        __syncthreads();
        S.starts[tid + 1] = cv + (wid ? S.wsumI[wid - 1] : 0);
        if (tid == 0) S.starts[0] = 0;
        __syncthreads();
        if (tid == 0) S.starts[1025] = S.starts[1024] + S.cnt[1024];
        __syncthreads();
    }
    for (int i = tid; i < 1025; i += 1024) S.cnt[i] = 0;
    __syncthreads();
    {
        int pos = S.starts[kk] + atomicAdd(&S.cnt[kk], 1);
        gQC[bh * 1024 + pos]   = make_float2(c1c, c2c);
        gQOut[bh * 1024 + pos] = (unsigned short)tid;
    }
    for (int i = tid; i < 1026; i += 1024) gStarts[bh * 1026 + i] = S.starts[i];
}

// ---------------------------------------------------------------------------
// vecB1: segment totals, wide. Grid (32 bh, 4) x 256. Warp = one segment:
// 32 coalesced row-gathers + FMA2, write gTot. No redundancy.
// ---------------------------------------------------------------------------
__global__ __launch_bounds__(256) void vecB1() {
    __shared__ unsigned short sPm[256];
    __shared__ float2         sE[256];

    const int bh = blockIdx.x, y = blockIdx.y;
    const int b = bh >> 2, head = bh & 3;
    const int tid = threadIdx.x, lane = tid & 31, wid = tid >> 5;
    const int base = bh * 1024 + y * 256;

    sPm[tid] = gPerm[base + tid];
    sE[tid]  = gE[base + tid];
    __syncthreads();

    const float* hhead = gH + (size_t)b * 1024 * 128 + head * 32;
    const int j0 = wid * 32;
    float t1 = 0.f, t2 = 0.f;
#pragma unroll
    for (int jj = 0; jj < 32; jj++) {
        float  hv = hhead[(size_t)sPm[j0 + jj] * 128 + lane];
        float2 ee = sE[j0 + jj];
        t1 = fmaf(ee.x, hv, t1);
        t2 = fmaf(ee.y, hv, t2);
    }
    gTot[(bh * 32 + y * 8 + wid) * 32 + lane] = make_float2(t1, t2);
}

// ---------------------------------------------------------------------------
// vecB2e: merge-emit, wide. Grid (32 bh, 4) x 256. Warp = one emit segment.
// Offsets from gTot (staged in smem); rows pre-gathered to 32 registers;
// queries staged in smem. Summation order identical to narrow version.
// ---------------------------------------------------------------------------
__global__ __launch_bounds__(256) void vecB2e(float* __restrict__ out) {
    __shared__ float2         sTot[32][32];     // 8 KB
    __shared__ unsigned short sPm[256];
    __shared__ float2         sE[256];
    __shared__ int            sStarts[258];
    __shared__ float2         sQc[1024];
    __shared__ unsigned short sQo[1024];

    const int bh = blockIdx.x, y = blockIdx.y;
    const int b = bh >> 2, head = bh & 3;
    const int tid = threadIdx.x, lane = tid & 31, wid = tid >> 5;
    const int base = bh * 1024 + y * 256;

    for (int i = tid; i < 1024; i += 256) sTot[i >> 5][i & 31] = gTot[bh * 1024 + i];
    sPm[tid] = gPerm[base + tid];
    sE[tid]  = gE[base + tid];
    for (int i = tid; i < 258; i += 256) sStarts[i] = gStarts[bh * 1026 + y * 256 + i];
    __syncthreads();

    const int q0   = sStarts[0];
    const int qEnd = (y == 3) ? sStarts[257] : sStarts[256];
    for (int t = tid; t < qEnd - q0; t += 256) {
        sQc[t] = gQC[bh * 1024 + q0 + t];
        sQo[t] = gQOut[bh * 1024 + q0 + t];
    }
    __syncthreads();

    // offsets + grand total (same order as narrow version)
    const int emitSeg = y * 8 + wid;
    float tv1 = 0.f, off1 = 0.f, off2 = 0.f;
#pragma unroll
    for (int t = 0; t < 32; t++) {
        float2 tt = sTot[t][lane];
        tv1 += tt.x;
        if (t < emitSeg) { off1 += tt.x; off2 += tt.y; }
    }

    // pre-gather this segment's 32 rows into registers (independent loads)
    const float* hhead = gH + (size_t)b * 1024 * 128 + head * 32;
    const int    j0    = wid * 32;      // local within block
    float hv[32];
#pragma unroll
    for (int jj = 0; jj < 32; jj++)
        hv[jj] = hhead[(size_t)sPm[j0 + jj] * 128 + lane];

    // merge-emit
    float acc1 = off1, acc2 = off2;
    int    qp = sStarts[j0];
    float* ob = out + (size_t)(b * 1024) * 128 + head * 32 + lane;

#pragma unroll
    for (int jj = 0; jj < 32; jj++) {
        int qe = sStarts[j0 + jj + 1];
        while (qp < qe) {
            float2 cc = sQc[qp - q0];
            int    i  = sQo[qp - q0];
            ob[(size_t)i * 128] = fmaf(cc.x, tv1 - acc1, cc.y * acc2);
            qp++;
        }
        float2 ee = sE[j0 + jj];
        acc1 = fmaf(ee.x, hv[jj], acc1);
        acc2 = fmaf(ee.y, hv[jj], acc2);
    }
    if (emitSeg == 31) {                 // bucket k == 1024 (y==3, wid==7)
        int qT = sStarts[257];
        while (qp < qT) {
            float2 cc = sQc[qp - q0];
            int    i  = sQo[qp - q0];
            ob[(size_t)i * 128] = fmaf(cc.x, tv1 - acc1, cc.y * acc2);
            qp++;
        }
    }
}

// ---------------------------------------------------------------------------
extern "C" void kernel_launch(void* const* d_in, const int* in_sizes, int n_in,
                              void* d_out, int out_size) {
    const float* x     = (const float*)d_in[0];
    const float* W     = (const float*)d_in[1];
    const float* a_src = (const float*)d_in[2];
    const float* a_dst = (const float*)d_in[3];
    float*       out   = (float*)d_out;

    const int smemA = (int)(sizeof(ScalS) > sizeof(GemmS) ? sizeof(ScalS) : sizeof(GemmS));
    static int smem_set = 0;
    if (!smem_set) {
        cudaFuncSetAttribute(fusedA, cudaFuncAttributeMaxDynamicSharedMemorySize, smemA);
        smem_set = 1;
    }

    fusedA<<<96, 1024, smemA>>>(x, W, a_src, a_dst);
    vecB1<<<dim3(32, 4), 256>>>();
    vecB2e<<<dim3(32, 4), 256>>>(out);
}